// round 15
// baseline (speedup 1.0000x reference)
#include <cuda_runtime.h>
#include <math.h>

#define BB   8
#define SEQ  2048
#define D    512
#define CWIN 16
#define NCH  128
#define DP   1536

typedef unsigned long long u64;

// ---------------- persistent device scratch ----------------
__device__ float g_KVQ[(size_t)BB*SEQ*1536];   // per token: [k 512 | v 512 | q 512]
__device__ float g_W3[1536*512];               // [Wk; Wv; Wqk@Wq]
__device__ float g_Y[BB*SEQ*D];
__device__ float g_S2[(size_t)BB*1024*D];      // S rows 1,2 only
__device__ float g_Xlast[BB*NCH*D];
__device__ float g_QG[BB*NCH*D];
__device__ float g_T[BB*NCH*D];
__device__ float g_gamma[BB*NCH*CWIN];
__device__ float g_alpha[BB*NCH];
__device__ float g_theta[BB*NCH];
__device__ float g_eta[BB*NCH];
__device__ float g_part2[2*BB*16];
__device__ float g_snorm[2*BB];
__device__ unsigned int g_ctr[BB];
__device__ unsigned int g_ctr2[BB];

// ---------------- f32x2 packed helpers (sm_100+) ----------------
__device__ __forceinline__ u64 PK2(float lo, float hi){
    u64 r; asm("mov.b64 %0, {%1,%2};" : "=l"(r) : "f"(lo), "f"(hi)); return r;
}
__device__ __forceinline__ void UNPK(u64 v, float& a, float& b){
    asm("mov.b64 {%0,%1}, %2;" : "=f"(a), "=f"(b) : "l"(v));
}
__device__ __forceinline__ u64 FMA2(u64 a, u64 b, u64 c){
    u64 d; asm("fma.rn.f32x2 %0,%1,%2,%3;" : "=l"(d) : "l"(a), "l"(b), "l"(c)); return d;
}
__device__ __forceinline__ u64 MUL2(u64 a, u64 b){
    u64 d; asm("mul.rn.f32x2 %0,%1,%2;" : "=l"(d) : "l"(a), "l"(b)); return d;
}
__device__ __forceinline__ u64 ADD2(u64 a, u64 b){
    u64 d; asm("add.rn.f32x2 %0,%1,%2;" : "=l"(d) : "l"(a), "l"(b)); return d;
}

__device__ __forceinline__ float wred(float x){
    #pragma unroll
    for (int o=16;o;o>>=1) x += __shfl_down_sync(0xffffffffu, x, o);
    return x;
}

// ---------------- fp32 GEMM: double-buffered, 2 CTAs/SM (R13 version) -----
template<bool NT>
__global__ void __launch_bounds__(256,2) gemm_kernel(const float* __restrict__ A,
                                                     const float* __restrict__ Bm,
                                                     float* __restrict__ Cm,
                                                     int M, int N, int K)
{
    __shared__ float As[2][16][132];
    __shared__ float Bs[2][16][132];
    int tid = threadIdx.x;
    int m0 = blockIdx.y * 128, n0 = blockIdx.x * 128;
    int ty = tid >> 4, tx = tid & 15;

    int row0 = tid >> 2,          k40 = (tid & 3)*4;
    int row1 = (tid+256) >> 2,    k41 = k40;
    int kr0  = tid >> 5,          n40 = (tid & 31)*4;
    int kr1  = (tid+256) >> 5,    n41 = n40;

    u64 acc2[8][4];
    #pragma unroll
    for (int i=0;i<8;i++)
        #pragma unroll
        for (int j=0;j<4;j++) acc2[i][j]=0ull;

    float4 ra0, ra1, rb0, rb1;

    ra0 = *(const float4*)(A + (size_t)(m0+row0)*K + k40);
    ra1 = *(const float4*)(A + (size_t)(m0+row1)*K + k41);
    if (NT){
        rb0 = *(const float4*)(Bm + (size_t)(n0+row0)*K + k40);
        rb1 = *(const float4*)(Bm + (size_t)(n0+row1)*K + k41);
    } else {
        rb0 = *(const float4*)(Bm + (size_t)(kr0)*N + n0 + n40);
        rb1 = *(const float4*)(Bm + (size_t)(kr1)*N + n0 + n41);
    }
    As[0][k40+0][row0]=ra0.x; As[0][k40+1][row0]=ra0.y; As[0][k40+2][row0]=ra0.z; As[0][k40+3][row0]=ra0.w;
    As[0][k41+0][row1]=ra1.x; As[0][k41+1][row1]=ra1.y; As[0][k41+2][row1]=ra1.z; As[0][k41+3][row1]=ra1.w;
    if (NT){
        Bs[0][k40+0][row0]=rb0.x; Bs[0][k40+1][row0]=rb0.y; Bs[0][k40+2][row0]=rb0.z; Bs[0][k40+3][row0]=rb0.w;
        Bs[0][k41+0][row1]=rb1.x; Bs[0][k41+1][row1]=rb1.y; Bs[0][k41+2][row1]=rb1.z; Bs[0][k41+3][row1]=rb1.w;
    } else {
        *(float4*)&Bs[0][kr0][n40] = rb0;
        *(float4*)&Bs[0][kr1][n41] = rb1;
    }
    __syncthreads();

    int nk = K >> 4;
    for (int t=0;t<nk;t++){
        if (t+1 < nk){
            int k0 = (t+1)*16;
            ra0 = *(const float4*)(A + (size_t)(m0+row0)*K + k0 + k40);
            ra1 = *(const float4*)(A + (size_t)(m0+row1)*K + k0 + k41);
            if (NT){
                rb0 = *(const float4*)(Bm + (size_t)(n0+row0)*K + k0 + k40);
                rb1 = *(const float4*)(Bm + (size_t)(n0+row1)*K + k0 + k41);
            } else {
                rb0 = *(const float4*)(Bm + (size_t)(k0+kr0)*N + n0 + n40);
                rb1 = *(const float4*)(Bm + (size_t)(k0+kr1)*N + n0 + n41);
            }
        }
        int bf = t & 1;
        #pragma unroll
        for (int kk=0;kk<16;kk++){
            float a[8];
            *(float4*)(a)   = *(const float4*)&As[bf][kk][ty*8];
            *(float4*)(a+4) = *(const float4*)&As[bf][kk][ty*8+4];
            u64 b2[4];
            *(ulonglong2*)&b2[0] = *(const ulonglong2*)&Bs[bf][kk][tx*8];
            *(ulonglong2*)&b2[2] = *(const ulonglong2*)&Bs[bf][kk][tx*8+4];
            #pragma unroll
            for (int i=0;i<8;i++){
                u64 ai = PK2(a[i], a[i]);
                #pragma unroll
                for (int jp=0;jp<4;jp++) acc2[i][jp] = FMA2(ai, b2[jp], acc2[i][jp]);
            }
        }
        if (t+1 < nk){
            int nb = (t+1) & 1;
            As[nb][k40+0][row0]=ra0.x; As[nb][k40+1][row0]=ra0.y; As[nb][k40+2][row0]=ra0.z; As[nb][k40+3][row0]=ra0.w;
            As[nb][k41+0][row1]=ra1.x; As[nb][k41+1][row1]=ra1.y; As[nb][k41+2][row1]=ra1.z; As[nb][k41+3][row1]=ra1.w;
            if (NT){
                Bs[nb][k40+0][row0]=rb0.x; Bs[nb][k40+1][row0]=rb0.y; Bs[nb][k40+2][row0]=rb0.z; Bs[nb][k40+3][row0]=rb0.w;
                Bs[nb][k41+0][row1]=rb1.x; Bs[nb][k41+1][row1]=rb1.y; Bs[nb][k41+2][row1]=rb1.z; Bs[nb][k41+3][row1]=rb1.w;
            } else {
                *(float4*)&Bs[nb][kr0][n40] = rb0;
                *(float4*)&Bs[nb][kr1][n41] = rb1;
            }
            __syncthreads();
        }
    }
    #pragma unroll
    for (int i=0;i<8;i++){
        float o[8];
        #pragma unroll
        for (int jp=0;jp<4;jp++) UNPK(acc2[i][jp], o[2*jp], o[2*jp+1]);
        size_t r = (size_t)(m0 + ty*8 + i)*N + n0 + tx*8;
        *(float4*)(Cm + r)     = make_float4(o[0],o[1],o[2],o[3]);
        *(float4*)(Cm + r + 4) = make_float4(o[4],o[5],o[6],o[7]);
    }
}

// ---------------- gather last token of each chunk ----------------
__global__ void gather_xlast(const float* __restrict__ x){
    int i = blockIdx.x*256 + threadIdx.x;
    if (i < BB*NCH*D){
        int e = i & 511; int r = i >> 9; int b = r >> 7; int n = r & 127;
        g_Xlast[i] = x[((size_t)b*SEQ + n*CWIN + (CWIN-1))*D + e];
    }
}

__global__ void zero_ctrs(){
    int i = threadIdx.x;
    if (i < BB){ g_ctr[i] = 0u; g_ctr2[i] = 0u; }
}

// ---------------- gates ----------------
__global__ void __launch_bounds__(128) gates_kernel(const float* __restrict__ x,
    const float* __restrict__ temp,
    const float* __restrict__ aw, const float* __restrict__ ab,
    const float* __restrict__ tw, const float* __restrict__ tb,
    const float* __restrict__ ew, const float* __restrict__ eb)
{
    int r = blockIdx.x; int b = r >> 7; int n = r & 127;
    int tid = threadIdx.x, w = tid >> 5, lane = tid & 31;
    __shared__ float ts[512];
    __shared__ float accA[16], accT[16], accE[16];
    for (int i=tid;i<512;i+=128) ts[i] = g_T[(size_t)r*512 + i];
    __syncthreads();
    float invt = 1.0f/(22.627416997969522f * fmaxf(temp[0], 0.1f));
    for (int c=w;c<16;c+=4){
        const float* xr = x + ((size_t)b*SEQ + n*CWIN + c)*D;
        float gs=0.f, as=0.f, tws=0.f, es=0.f;
        for (int e=lane;e<512;e+=32){
            float xv = xr[e];
            gs  = fmaf(xv, ts[e], gs);
            as  = fmaf(xv, aw[e], as);
            tws = fmaf(xv, tw[e], tws);
            es  = fmaf(xv, ew[e], es);
        }
        gs = wred(gs); as = wred(as); tws = wred(tws); es = wred(es);
        if (lane==0){
            g_gamma[(size_t)r*CWIN + c] = 1.f/(1.f + expf(-gs*invt));
            accA[c]=as; accT[c]=tws; accE[c]=es;
        }
    }
    __syncthreads();
    if (tid==0){
        float sa=0.f, st=0.f, se=0.f;
        for (int c=0;c<16;c++){ sa+=accA[c]; st+=accT[c]; se+=accE[c]; }
        sa = sa*(1.f/16.f) + ab[0];
        st = st*(1.f/16.f) + tb[0];
        se = se*(1.f/16.f) + eb[0];
        g_alpha[r] = 1.f/(1.f+expf(-sa));
        g_theta[r] = 1.f/(1.f+expf(-st));
        g_eta[r]   = 1.f/(1.f+expf(-se));
    }
}

// ---------------- persistent chunk-recurrence kernel ----------------
// R13 structure + (a) KS(n+1) staged by all threads right after the early
// norm publish (overlaps B2, off the serial top), (b) last-arriver norm
// aggregation: one block sums partials and publishes a single scalar.
#define SM_KS    0           // u64[512*18]  splat (k,k)     73728 B
#define SM_QS    73728       // u64[512*18]  splat (q,q)     73728 B
#define SM_RED   147456      // u64[16*16*16]                32768 B
#define SM_ERS2  180224      // u64[16 pi][16 c]              2048 B
#define SM_WRS   182272      // float[16]
#define SM_SBC   182336      // float
#define SM_PM0   182400      // u64[16]
#define SM_YM0   182528      // u64[16]
#define SM_SQM   182656      // u64[16]
#define SM_TOT   182784

__global__ void __launch_bounds__(512,1) chunk_loop_kernel(const float* __restrict__ coeffs,
                                                           const float* __restrict__ M0g,
                                                           const float* __restrict__ S0g)
{
    extern __shared__ char smraw[];
    u64*   KS   = (u64*)(smraw + SM_KS);
    u64*   QS   = (u64*)(smraw + SM_QS);
    u64*   RED  = (u64*)(smraw + SM_RED);
    u64*   ERS2 = (u64*)(smraw + SM_ERS2);
    float* WRS  = (float*)(smraw + SM_WRS);
    float* SBC  = (float*)(smraw + SM_SBC);
    u64*   PM0  = (u64*)(smraw + SM_PM0);
    u64*   YM0  = (u64*)(smraw + SM_YM0);
    u64*   SQM  = (u64*)(smraw + SM_SQM);

    const int b = blockIdx.y, vt = blockIdx.x;
    const int tid = threadIdx.x;
    const int pi = tid & 15, jg = tid >> 4;
    const int w = tid >> 5, lane = tid & 31;
    const int v0 = vt*32 + 2*pi;
    const int rc = tid >> 4, rpi = tid & 15;

    const float c0 = coeffs[0], c1 = coeffs[1], c2 = coeffs[2];
    const u64 c0_2 = PK2(c0,c0), c1_2 = PK2(c1,c1), c2_2 = PK2(c2,c2);
    const float f0 = 0.125f*c0, f1 = 0.125f*c1, f2 = 0.125f*c2;

    const float* M0b = M0g + (size_t)b*DP*D;
    const float* S0b = S0g + (size_t)b*DP*D;
    float* Sw = g_S2 + (size_t)b*1024*D;

    // ---- initial row-0 moments (threads tid<16) ----
    u64 Mm1=0ull, Ms1=0ull, Mm2=0ull, Ms2=0ull, Mms=0ull;
    if (tid < 16){
        const float* pm = M0b + vt*32 + 2*tid;
        const float* ps = S0b + vt*32 + 2*tid;
        #pragma unroll 4
        for (int j=0;j<512;j++){
            u64 m = *(const u64*)(pm + (size_t)j*D);
            u64 s = *(const u64*)(ps + (size_t)j*D);
            Mm1 = ADD2(Mm1, m); Ms1 = ADD2(Ms1, s);
            Mm2 = FMA2(m,m,Mm2); Ms2 = FMA2(s,s,Ms2); Mms = FMA2(m,s,Mms);
        }
    }

    // ---- initial register state: rows 1,2 of M ----
    u64 rM1[16], rM2[16];
    #pragma unroll
    for (int t=0;t<16;t++){
        const float* pm = M0b + (size_t)(512 + jg + 32*t)*D + v0;
        rM1[t] = *(const u64*)pm;
        rM2[t] = *(const u64*)(pm + 512*D);
    }

    // ---- prologue: stage k_0 (all threads) ----
    {
        const float* Kc = g_KVQ + (size_t)b*SEQ*1536;
        #pragma unroll
        for (int i=0;i<16;i++){
            int idx = tid + i*512;
            int j = idx & 511, c = idx >> 9;
            float kv = Kc[(size_t)c*1536 + j];
            KS[j*18 + c] = PK2(kv,kv);
        }
    }

    u64 yv_pend = 0ull;

    for (int n=0;n<NCH;n++){
        // ---- top: publish pre-update ΣM0; stage q_n only ----
        if (tid < 16) PM0[tid] = Mm1;
        {
            const float* Qc = g_KVQ + ((size_t)b*SEQ + n*CWIN)*1536 + 1024;
            #pragma unroll
            for (int i=0;i<16;i++){
                int idx = tid + i*512;
                int j = idx & 511, c = idx >> 9;
                float qv = Qc[(size_t)c*1536 + j];
                QS[j*18 + c] = PK2(qv,qv);
            }
        }
        __syncthreads();                                 // sync1

        // ---- phase A: pred partials (M from registers) ----
        u64 acc[16];
        #pragma unroll
        for (int c=0;c<16;c++) acc[c]=0ull;
        #pragma unroll
        for (int t=0;t<16;t++){
            u64 t1 = MUL2(c1_2, rM1[t]), t2 = MUL2(c2_2, rM2[t]);
            const ulonglong2* kp = (const ulonglong2*)&KS[(jg + 32*t)*18];
            #pragma unroll
            for (int cc=0;cc<8;cc++){
                ulonglong2 kk = kp[cc];
                acc[2*cc]   = FMA2(kk.x, FMA2(kk.x, t2, t1), acc[2*cc]);
                acc[2*cc+1] = FMA2(kk.y, FMA2(kk.y, t2, t1), acc[2*cc+1]);
            }
        }
        #pragma unroll
        for (int c=0;c<16;c++){
            acc[c] = ADD2(acc[c], __shfl_down_sync(0xffffffffu, acc[c], 16));
            if (lane < 16) RED[(w*16 + c)*16 + lane] = acc[c];
        }
        __syncthreads();                                 // sync2

        // ---- pred reduce; prefetch V/gamma/gates; overlapped norm wait ----
        u64 p2 = 0ull;
        float2 vv = make_float2(0.f,0.f);
        float ga = 0.f;
        if (tid < 256){
            u64 ps = 0ull;
            #pragma unroll
            for (int g=0;g<16;g++) ps = ADD2(ps, RED[(g*16 + rc)*16 + rpi]);
            p2 = FMA2(c0_2, PM0[rpi], ps);
            vv = *(const float2*)(g_KVQ + ((size_t)b*SEQ + n*CWIN + rc)*1536 + 512 + vt*32 + 2*rpi);
            ga = g_gamma[(b*NCH + n)*CWIN + rc];
        }
        int gi = b*NCH + n;
        float alf0 = g_alpha[gi], thf = g_theta[gi], etf = g_eta[gi];
        if (tid==0 && n>0){
            while (atomicAdd(&g_ctr2[b], 0u) < (unsigned)n) __nanosleep(32);
            __threadfence();
            SBC[0] = __ldcg(&g_snorm[((n-1)&1)*BB + b]);
        }
        __syncthreads();                                 // sync3
        float s_prev = (n>0) ? SBC[0] : 1.0f;

        // ---- write pending y(n-1), compute err(n) ----
        if (tid < 256){
            if (n>0){
                float ya,yb; UNPK(yv_pend, ya, yb);
                *(float2*)&g_Y[((size_t)b*SEQ + (n-1)*CWIN + rc)*D + vt*32 + 2*rpi]
                    = make_float2(s_prev*ya, s_prev*yb);
            }
            float pa,pb; UNPK(p2, pa, pb);
            float ea = ga*(pa*s_prev - vv.x);
            float eb = ga*(pb*s_prev - vv.y);
            ERS2[rpi*16 + rc] = PK2(ea, eb);
        }
        __syncthreads();                                 // sync4

        float alf = alf0*s_prev;

        // ---- row-0 moment update (threads tid<16) ----
        if (tid < 16){
            u64 esum = 0ull;
            #pragma unroll
            for (int c=0;c<16;c++) esum = ADD2(esum, ERS2[tid*16 + c]);
            float ge = etf*f0;
            u64 g   = MUL2(PK2(ge,ge), esum);
            u64 thv = PK2(thf,thf), alv = PK2(alf,alf);
            u64 s1n = FMA2(thv, Ms1, MUL2(PK2(-512.f,-512.f), g));
            u64 thg = MUL2(thv, g);
            u64 s2n = ADD2( FMA2(MUL2(thv,thv), Ms2, MUL2(PK2(-2.f,-2.f), MUL2(thg, Ms1))),
                            MUL2(PK2(512.f,512.f), MUL2(g,g)) );
            u64 msp = FMA2(thv, Mms, MUL2(MUL2(PK2(-1.f,-1.f), g), Mm1));
            u64 m1n = FMA2(alv, Mm1, s1n);
            u64 m2n = ADD2( FMA2(MUL2(alv,alv), Mm2, MUL2(MUL2(PK2(2.f,2.f), alv), msp)), s2n );
            u64 msn = ADD2(MUL2(alv, msp), s2n);
            Mm1=m1n; Ms1=s1n; Mm2=m2n; Ms2=s2n; Mms=msn;
            YM0[tid] = m1n;
            SQM[tid] = m2n;
        }

        // ---- phase B1: grad + M-register update + S stream + sumsq ----
        u64 sq2 = 0ull;
        {
            u64 e2[16];
            #pragma unroll
            for (int c=0;c<16;c++) e2[c] = ERS2[pi*16 + c];

            u64 al = PK2(alf,alf), th = PK2(thf,thf);
            u64 nf1 = PK2(-etf*f1, -etf*f1);
            u64 nf2 = PK2(-etf*f2, -etf*f2);

            const float* Srd = (n==0) ? (S0b + (size_t)512*D) : Sw;
            const float* pR = Srd + (size_t)jg*D + v0;
            float*       pW = Sw  + (size_t)jg*D + v0;
            u64 so1 = *(const u64*)pR;
            u64 so2 = *(const u64*)(pR + 512*D);
            #pragma unroll
            for (int t=0;t<16;t++){
                const float* pRn = pR + 32*D;
                u64 nso1=0ull, nso2=0ull;
                if (t<15){ nso1 = *(const u64*)pRn; nso2 = *(const u64*)(pRn + 512*D); }
                const ulonglong2* kp = (const ulonglong2*)&KS[(jg + 32*t)*18];
                u64 g1 = 0ull, g2 = 0ull;
                #pragma unroll
                for (int cc=0;cc<8;cc++){
                    ulonglong2 kk = kp[cc];
                    u64 k2a = MUL2(kk.x, kk.x);
                    u64 k2b = MUL2(kk.y, kk.y);
                    g1 = FMA2(kk.x, e2[2*cc],   g1);
                    g2 = FMA2(k2a,  e2[2*cc],   g2);
                    g1 = FMA2(kk.y, e2[2*cc+1], g1);
                    g2 = FMA2(k2b,  e2[2*cc+1], g2);
                }
                u64 sn1 = FMA2(nf1, g1, MUL2(th, so1));
                u64 sn2 = FMA2(nf2, g2, MUL2(th, so2));
                u64 mn1 = FMA2(al, rM1[t], sn1);
                u64 mn2 = FMA2(al, rM2[t], sn2);
                *(u64*)(pW)         = sn1;
                *(u64*)(pW + 512*D) = sn2;
                rM1[t] = mn1; rM2[t] = mn2;
                sq2 = FMA2(mn1,mn1,sq2); sq2 = FMA2(mn2,mn2,sq2);
                so1 = nso1; so2 = nso2; pR = pRn; pW += 32*D;
            }
        }
        float sa,sb; UNPK(sq2, sa, sb);
        float sq = wred(sa + sb);
        if (lane==0) WRS[w] = sq;
        __syncthreads();                                 // sync4b

        // ---- EARLY norm publish; last arriver aggregates to one scalar ----
        if (tid==0){
            float tot = 0.f;
            #pragma unroll
            for (int i=0;i<16;i++) tot += WRS[i];
            #pragma unroll
            for (int i=0;i<16;i++){
                float qa,qb; UNPK(SQM[i], qa, qb);
                tot += qa + qb;
            }
            g_part2[(n&1)*BB*16 + b*16 + vt] = tot;
            __threadfence();
            unsigned old = atomicAdd(&g_ctr[b], 1u);
            if ((old & 15u) == 15u){
                __threadfence();
                float ss = 0.f;
                const float* pp = g_part2 + (n&1)*BB*16 + b*16;
                #pragma unroll
                for (int i=0;i<16;i++) ss += __ldcg(&pp[i]);
                g_snorm[(n&1)*BB + b] = fminf(50.0f/(sqrtf(ss)+1e-6f), 1.0f);
                __threadfence();
                atomicAdd(&g_ctr2[b], 1u);
            }
        }

        // ---- stage k_{n+1} (all threads; KS(n) dead, overlaps B2 latency) ----
        if (n < NCH-1){
            const float* Kc = g_KVQ + ((size_t)b*SEQ + (n+1)*CWIN)*1536;
            #pragma unroll
            for (int i=0;i<16;i++){
                int idx = tid + i*512;
                int j = idx & 511, c = idx >> 9;
                float kv = Kc[(size_t)c*1536 + j];
                KS[j*18 + c] = PK2(kv,kv);
            }
        }

        // ---- phase B2: y-read from updated M registers ----
        {
            u64 yacc[16];
            #pragma unroll
            for (int c=0;c<16;c++) yacc[c]=0ull;
            #pragma unroll
            for (int t=0;t<16;t++){
                u64 u1 = MUL2(c1_2, rM1[t]);
                u64 u2 = MUL2(c2_2, rM2[t]);
                const ulonglong2* qp = (const ulonglong2*)&QS[(jg + 32*t)*18];
                #pragma unroll
                for (int cc=0;cc<8;cc++){
                    ulonglong2 qq = qp[cc];
                    yacc[2*cc]   = FMA2(qq.x, FMA2(qq.x, u2, u1), yacc[2*cc]);
                    yacc[2*cc+1] = FMA2(qq.y, FMA2(qq.y, u2, u1), yacc[2*cc+1]);
                }
            }
            #pragma unroll
            for (int c=0;c<16;c++){
                yacc[c] = ADD2(yacc[c], __shfl_down_sync(0xffffffffu, yacc[c], 16));
                if (lane < 16) RED[(w*16 + c)*16 + lane] = yacc[c];
            }
        }
        __syncthreads();                                 // sync5

        if (tid < 256){
            u64 ys = 0ull;
            #pragma unroll
            for (int g=0;g<16;g++) ys = ADD2(ys, RED[(g*16 + rc)*16 + rpi]);
            yv_pend = FMA2(c0_2, YM0[rpi], ys);
        }
    }

    // ---- tail: y for chunk 127 ----
    __syncthreads();
    if (tid==0){
        while (atomicAdd(&g_ctr2[b], 0u) < (unsigned)NCH) __nanosleep(32);
        __threadfence();
        SBC[0] = __ldcg(&g_snorm[((NCH-1)&1)*BB + b]);
    }
    __syncthreads();
    if (tid < 256){
        float s = SBC[0];
        float ya,yb; UNPK(yv_pend, ya, yb);
        *(float2*)&g_Y[((size_t)b*SEQ + (NCH-1)*CWIN + rc)*D + vt*32 + 2*rpi]
            = make_float2(s*ya, s*yb);
    }
}

// ---------------- launch ----------------
extern "C" void kernel_launch(void* const* d_in, const int* in_sizes, int n_in,
                              void* d_out, int out_size)
{
    const float* x     = (const float*)d_in[0];
    const float* M0    = (const float*)d_in[1];
    const float* S0    = (const float*)d_in[2];
    const float* Wk    = (const float*)d_in[3];
    const float* Wv    = (const float*)d_in[4];
    const float* Wq    = (const float*)d_in[5];
    const float* Wqk   = (const float*)d_in[6];
    const float* Wout  = (const float*)d_in[7];
    const float* coeffs= (const float*)d_in[8];
    const float* cgWq  = (const float*)d_in[9];
    const float* cgWk  = (const float*)d_in[10];
    const float* temp  = (const float*)d_in[11];
    const float* aw    = (const float*)d_in[12];
    const float* ab    = (const float*)d_in[13];
    const float* tw    = (const float*)d_in[14];
    const float* tb    = (const float*)d_in[15];
    const float* ew    = (const float*)d_in[16];
    const float* eb    = (const float*)d_in[17];
    float* out = (float*)d_out;

    float *pKVQ,*pW3,*pY,*pXl,*pQG,*pT;
    cudaGetSymbolAddress((void**)&pKVQ, g_KVQ);
    cudaGetSymbolAddress((void**)&pW3,  g_W3);
    cudaGetSymbolAddress((void**)&pY,   g_Y);
    cudaGetSymbolAddress((void**)&pXl,  g_Xlast);
    cudaGetSymbolAddress((void**)&pQG,  g_QG);
    cudaGetSymbolAddress((void**)&pT,   g_T);

    cudaFuncSetAttribute(chunk_loop_kernel,
                         cudaFuncAttributeMaxDynamicSharedMemorySize, SM_TOT);

    zero_ctrs<<<1,32>>>();

    // W3 = [Wk; Wv; Wqk@Wq], then ONE merged projection GEMM
    cudaMemcpyAsync(pW3,          Wk, sizeof(float)*512*512, cudaMemcpyDeviceToDevice);
    cudaMemcpyAsync(pW3+512*512,  Wv, sizeof(float)*512*512, cudaMemcpyDeviceToDevice);
    gemm_kernel<false><<<dim3(4,4),  256>>>(Wqk, Wq, pW3+1024*512, 512, 512, 512);
    gemm_kernel<true ><<<dim3(12,128),256>>>(x, pW3, pKVQ, BB*SEQ, 1536, 512);

    // gates
    gather_xlast<<<2048,256>>>(x);
    gemm_kernel<true ><<<dim3(4,8),256>>>(pXl, cgWq, pQG, BB*NCH, 512, 512);
    gemm_kernel<false><<<dim3(4,8),256>>>(pQG, cgWk, pT,  BB*NCH, 512, 512);
    gates_kernel<<<BB*NCH,128>>>(x, temp, aw, ab, tw, tb, ew, eb);

    // entire 128-chunk recurrence in ONE persistent kernel (M in registers)
    chunk_loop_kernel<<<dim3(16,8),512,SM_TOT>>>(coeffs, M0, S0);

    // out = Y @ Wout^T
    gemm_kernel<true><<<dim3(4,128),256>>>(pY, Wout, out, BB*SEQ, 512, 512);
}

// round 16
// speedup vs baseline: 1.0482x; 1.0482x over previous
#include <cuda_runtime.h>
#include <math.h>

#define BB   8
#define SEQ  2048
#define D    512
#define CWIN 16
#define NCH  128
#define DP   1536

typedef unsigned long long u64;

// ---------------- persistent device scratch ----------------
__device__ float g_KVQ[(size_t)BB*SEQ*1536];   // per token: [k 512 | v 512 | q 512]
__device__ float g_W3[1536*512];               // [Wk; Wv; Wqk@Wq]
__device__ float g_Y[BB*SEQ*D];
__device__ float g_S2[(size_t)BB*1024*D];      // S rows 1,2 only
__device__ float g_Xlast[BB*NCH*D];
__device__ float g_QG[BB*NCH*D];
__device__ float g_T[BB*NCH*D];
__device__ float g_gamma[BB*NCH*CWIN];
__device__ float g_alpha[BB*NCH];
__device__ float g_theta[BB*NCH];
__device__ float g_eta[BB*NCH];
__device__ float g_part2[2*BB*16];
__device__ unsigned int g_ctr[BB];

// ---------------- f32x2 packed helpers (sm_100+) ----------------
__device__ __forceinline__ u64 PK2(float lo, float hi){
    u64 r; asm("mov.b64 %0, {%1,%2};" : "=l"(r) : "f"(lo), "f"(hi)); return r;
}
__device__ __forceinline__ void UNPK(u64 v, float& a, float& b){
    asm("mov.b64 {%0,%1}, %2;" : "=f"(a), "=f"(b) : "l"(v));
}
__device__ __forceinline__ u64 FMA2(u64 a, u64 b, u64 c){
    u64 d; asm("fma.rn.f32x2 %0,%1,%2,%3;" : "=l"(d) : "l"(a), "l"(b), "l"(c)); return d;
}
__device__ __forceinline__ u64 MUL2(u64 a, u64 b){
    u64 d; asm("mul.rn.f32x2 %0,%1,%2;" : "=l"(d) : "l"(a), "l"(b)); return d;
}
__device__ __forceinline__ u64 ADD2(u64 a, u64 b){
    u64 d; asm("add.rn.f32x2 %0,%1,%2;" : "=l"(d) : "l"(a), "l"(b)); return d;
}

__device__ __forceinline__ float wred(float x){
    #pragma unroll
    for (int o=16;o;o>>=1) x += __shfl_down_sync(0xffffffffu, x, o);
    return x;
}

// ---------------- fp32 GEMM: double-buffered, 2 CTAs/SM ----------------
template<bool NT>
__global__ void __launch_bounds__(256,2) gemm_kernel(const float* __restrict__ A,
                                                     const float* __restrict__ Bm,
                                                     float* __restrict__ Cm,
                                                     int M, int N, int K)
{
    __shared__ float As[2][16][132];
    __shared__ float Bs[2][16][132];
    int tid = threadIdx.x;
    int m0 = blockIdx.y * 128, n0 = blockIdx.x * 128;
    int ty = tid >> 4, tx = tid & 15;

    int row0 = tid >> 2,          k40 = (tid & 3)*4;
    int row1 = (tid+256) >> 2,    k41 = k40;
    int kr0  = tid >> 5,          n40 = (tid & 31)*4;
    int kr1  = (tid+256) >> 5,    n41 = n40;

    u64 acc2[8][4];
    #pragma unroll
    for (int i=0;i<8;i++)
        #pragma unroll
        for (int j=0;j<4;j++) acc2[i][j]=0ull;

    float4 ra0, ra1, rb0, rb1;

    ra0 = *(const float4*)(A + (size_t)(m0+row0)*K + k40);
    ra1 = *(const float4*)(A + (size_t)(m0+row1)*K + k41);
    if (NT){
        rb0 = *(const float4*)(Bm + (size_t)(n0+row0)*K + k40);
        rb1 = *(const float4*)(Bm + (size_t)(n0+row1)*K + k41);
    } else {
        rb0 = *(const float4*)(Bm + (size_t)(kr0)*N + n0 + n40);
        rb1 = *(const float4*)(Bm + (size_t)(kr1)*N + n0 + n41);
    }
    As[0][k40+0][row0]=ra0.x; As[0][k40+1][row0]=ra0.y; As[0][k40+2][row0]=ra0.z; As[0][k40+3][row0]=ra0.w;
    As[0][k41+0][row1]=ra1.x; As[0][k41+1][row1]=ra1.y; As[0][k41+2][row1]=ra1.z; As[0][k41+3][row1]=ra1.w;
    if (NT){
        Bs[0][k40+0][row0]=rb0.x; Bs[0][k40+1][row0]=rb0.y; Bs[0][k40+2][row0]=rb0.z; Bs[0][k40+3][row0]=rb0.w;
        Bs[0][k41+0][row1]=rb1.x; Bs[0][k41+1][row1]=rb1.y; Bs[0][k41+2][row1]=rb1.z; Bs[0][k41+3][row1]=rb1.w;
    } else {
        *(float4*)&Bs[0][kr0][n40] = rb0;
        *(float4*)&Bs[0][kr1][n41] = rb1;
    }
    __syncthreads();

    int nk = K >> 4;
    for (int t=0;t<nk;t++){
        if (t+1 < nk){
            int k0 = (t+1)*16;
            ra0 = *(const float4*)(A + (size_t)(m0+row0)*K + k0 + k40);
            ra1 = *(const float4*)(A + (size_t)(m0+row1)*K + k0 + k41);
            if (NT){
                rb0 = *(const float4*)(Bm + (size_t)(n0+row0)*K + k0 + k40);
                rb1 = *(const float4*)(Bm + (size_t)(n0+row1)*K + k0 + k41);
            } else {
                rb0 = *(const float4*)(Bm + (size_t)(k0+kr0)*N + n0 + n40);
                rb1 = *(const float4*)(Bm + (size_t)(k0+kr1)*N + n0 + n41);
            }
        }
        int bf = t & 1;
        #pragma unroll
        for (int kk=0;kk<16;kk++){
            float a[8];
            *(float4*)(a)   = *(const float4*)&As[bf][kk][ty*8];
            *(float4*)(a+4) = *(const float4*)&As[bf][kk][ty*8+4];
            u64 b2[4];
            *(ulonglong2*)&b2[0] = *(const ulonglong2*)&Bs[bf][kk][tx*8];
            *(ulonglong2*)&b2[2] = *(const ulonglong2*)&Bs[bf][kk][tx*8+4];
            #pragma unroll
            for (int i=0;i<8;i++){
                u64 ai = PK2(a[i], a[i]);
                #pragma unroll
                for (int jp=0;jp<4;jp++) acc2[i][jp] = FMA2(ai, b2[jp], acc2[i][jp]);
            }
        }
        if (t+1 < nk){
            int nb = (t+1) & 1;
            As[nb][k40+0][row0]=ra0.x; As[nb][k40+1][row0]=ra0.y; As[nb][k40+2][row0]=ra0.z; As[nb][k40+3][row0]=ra0.w;
            As[nb][k41+0][row1]=ra1.x; As[nb][k41+1][row1]=ra1.y; As[nb][k41+2][row1]=ra1.z; As[nb][k41+3][row1]=ra1.w;
            if (NT){
                Bs[nb][k40+0][row0]=rb0.x; Bs[nb][k40+1][row0]=rb0.y; Bs[nb][k40+2][row0]=rb0.z; Bs[nb][k40+3][row0]=rb0.w;
                Bs[nb][k41+0][row1]=rb1.x; Bs[nb][k41+1][row1]=rb1.y; Bs[nb][k41+2][row1]=rb1.z; Bs[nb][k41+3][row1]=rb1.w;
            } else {
                *(float4*)&Bs[nb][kr0][n40] = rb0;
                *(float4*)&Bs[nb][kr1][n41] = rb1;
            }
            __syncthreads();
        }
    }
    #pragma unroll
    for (int i=0;i<8;i++){
        float o[8];
        #pragma unroll
        for (int jp=0;jp<4;jp++) UNPK(acc2[i][jp], o[2*jp], o[2*jp+1]);
        size_t r = (size_t)(m0 + ty*8 + i)*N + n0 + tx*8;
        *(float4*)(Cm + r)     = make_float4(o[0],o[1],o[2],o[3]);
        *(float4*)(Cm + r + 4) = make_float4(o[4],o[5],o[6],o[7]);
    }
}

// ---------------- gather last token of each chunk ----------------
__global__ void gather_xlast(const float* __restrict__ x){
    int i = blockIdx.x*256 + threadIdx.x;
    if (i < BB*NCH*D){
        int e = i & 511; int r = i >> 9; int b = r >> 7; int n = r & 127;
        g_Xlast[i] = x[((size_t)b*SEQ + n*CWIN + (CWIN-1))*D + e];
    }
}

__global__ void zero_ctrs(){
    int i = threadIdx.x;
    if (i < BB) g_ctr[i] = 0u;
}

// ---------------- gates ----------------
__global__ void __launch_bounds__(128) gates_kernel(const float* __restrict__ x,
    const float* __restrict__ temp,
    const float* __restrict__ aw, const float* __restrict__ ab,
    const float* __restrict__ tw, const float* __restrict__ tb,
    const float* __restrict__ ew, const float* __restrict__ eb)
{
    int r = blockIdx.x; int b = r >> 7; int n = r & 127;
    int tid = threadIdx.x, w = tid >> 5, lane = tid & 31;
    __shared__ float ts[512];
    __shared__ float accA[16], accT[16], accE[16];
    for (int i=tid;i<512;i+=128) ts[i] = g_T[(size_t)r*512 + i];
    __syncthreads();
    float invt = 1.0f/(22.627416997969522f * fmaxf(temp[0], 0.1f));
    for (int c=w;c<16;c+=4){
        const float* xr = x + ((size_t)b*SEQ + n*CWIN + c)*D;
        float gs=0.f, as=0.f, tws=0.f, es=0.f;
        for (int e=lane;e<512;e+=32){
            float xv = xr[e];
            gs  = fmaf(xv, ts[e], gs);
            as  = fmaf(xv, aw[e], as);
            tws = fmaf(xv, tw[e], tws);
            es  = fmaf(xv, ew[e], es);
        }
        gs = wred(gs); as = wred(as); tws = wred(tws); es = wred(es);
        if (lane==0){
            g_gamma[(size_t)r*CWIN + c] = 1.f/(1.f + expf(-gs*invt));
            accA[c]=as; accT[c]=tws; accE[c]=es;
        }
    }
    __syncthreads();
    if (tid==0){
        float sa=0.f, st=0.f, se=0.f;
        for (int c=0;c<16;c++){ sa+=accA[c]; st+=accT[c]; se+=accE[c]; }
        sa = sa*(1.f/16.f) + ab[0];
        st = st*(1.f/16.f) + tb[0];
        se = se*(1.f/16.f) + eb[0];
        g_alpha[r] = 1.f/(1.f+expf(-sa));
        g_theta[r] = 1.f/(1.f+expf(-st));
        g_eta[r]   = 1.f/(1.f+expf(-se));
    }
}

// ---------------- persistent chunk-recurrence kernel (R13 + S prefetch) ----
#define SM_KS    0           // u64[512*18]  splat (k,k)     73728 B
#define SM_QS    73728       // u64[512*18]  splat (q,q)     73728 B
#define SM_RED   147456      // u64[16*16*16]                32768 B
#define SM_ERS2  180224      // u64[16 pi][16 c]              2048 B
#define SM_WRS   182272      // float[16]
#define SM_SBC   182336      // float
#define SM_PM0   182400      // u64[16]
#define SM_YM0   182528      // u64[16]
#define SM_SQM   182656      // u64[16]
#define SM_TOT   182784

__global__ void __launch_bounds__(512,1) chunk_loop_kernel(const float* __restrict__ coeffs,
                                                           const float* __restrict__ M0g,
                                                           const float* __restrict__ S0g)
{
    extern __shared__ char smraw[];
    u64*   KS   = (u64*)(smraw + SM_KS);
    u64*   QS   = (u64*)(smraw + SM_QS);
    u64*   RED  = (u64*)(smraw + SM_RED);
    u64*   ERS2 = (u64*)(smraw + SM_ERS2);
    float* WRS  = (float*)(smraw + SM_WRS);
    float* SBC  = (float*)(smraw + SM_SBC);
    u64*   PM0  = (u64*)(smraw + SM_PM0);
    u64*   YM0  = (u64*)(smraw + SM_YM0);
    u64*   SQM  = (u64*)(smraw + SM_SQM);

    const int b = blockIdx.y, vt = blockIdx.x;
    const int tid = threadIdx.x;
    const int pi = tid & 15, jg = tid >> 4;
    const int w = tid >> 5, lane = tid & 31;
    const int v0 = vt*32 + 2*pi;
    const int rc = tid >> 4, rpi = tid & 15;

    const float c0 = coeffs[0], c1 = coeffs[1], c2 = coeffs[2];
    const u64 c0_2 = PK2(c0,c0), c1_2 = PK2(c1,c1), c2_2 = PK2(c2,c2);
    const float f0 = 0.125f*c0, f1 = 0.125f*c1, f2 = 0.125f*c2;

    const float* M0b = M0g + (size_t)b*DP*D;
    const float* S0b = S0g + (size_t)b*DP*D;
    float* Sw = g_S2 + (size_t)b*1024*D;

    // ---- initial row-0 moments (threads tid<16) ----
    u64 Mm1=0ull, Ms1=0ull, Mm2=0ull, Ms2=0ull, Mms=0ull;
    if (tid < 16){
        const float* pm = M0b + vt*32 + 2*tid;
        const float* ps = S0b + vt*32 + 2*tid;
        #pragma unroll 4
        for (int j=0;j<512;j++){
            u64 m = *(const u64*)(pm + (size_t)j*D);
            u64 s = *(const u64*)(ps + (size_t)j*D);
            Mm1 = ADD2(Mm1, m); Ms1 = ADD2(Ms1, s);
            Mm2 = FMA2(m,m,Mm2); Ms2 = FMA2(s,s,Ms2); Mms = FMA2(m,s,Mms);
        }
    }

    // ---- initial register state: rows 1,2 of M (64 regs) ----
    u64 rM1[16], rM2[16];
    #pragma unroll
    for (int t=0;t<16;t++){
        const float* pm = M0b + (size_t)(512 + jg + 32*t)*D + v0;
        rM1[t] = *(const u64*)pm;
        rM2[t] = *(const u64*)(pm + 512*D);
    }

    u64 yv_pend = 0ull;

    for (int n=0;n<NCH;n++){
        // ---- publish pre-update ΣM0; co-stage k AND q splats (j-major) ----
        if (tid < 16) PM0[tid] = Mm1;
        const float* KQc = g_KVQ + ((size_t)b*SEQ + n*CWIN)*1536;
        #pragma unroll
        for (int i=0;i<16;i++){
            int idx = tid + i*512;
            int j = idx & 511, c = idx >> 9;
            float kv = KQc[(size_t)c*1536 + j];
            float qv = KQc[(size_t)c*1536 + 1024 + j];
            KS[j*18 + c] = PK2(kv,kv);
            QS[j*18 + c] = PK2(qv,qv);
        }
        __syncthreads();                                 // sync 1

        // ---- phase A: pred partials (M from registers) ----
        u64 acc[16];
        #pragma unroll
        for (int c=0;c<16;c++) acc[c]=0ull;
        #pragma unroll
        for (int t=0;t<16;t++){
            u64 t1 = MUL2(c1_2, rM1[t]), t2 = MUL2(c2_2, rM2[t]);
            const ulonglong2* kp = (const ulonglong2*)&KS[(jg + 32*t)*18];
            #pragma unroll
            for (int cc=0;cc<8;cc++){
                ulonglong2 kk = kp[cc];
                acc[2*cc]   = FMA2(kk.x, FMA2(kk.x, t2, t1), acc[2*cc]);
                acc[2*cc+1] = FMA2(kk.y, FMA2(kk.y, t2, t1), acc[2*cc+1]);
            }
        }
        #pragma unroll
        for (int c=0;c<16;c++){
            acc[c] = ADD2(acc[c], __shfl_down_sync(0xffffffffu, acc[c], 16));
            if (lane < 16) RED[(w*16 + c)*16 + lane] = acc[c];
        }
        __syncthreads();                                 // sync 2

        // ---- EARLY S prefetch for B1 (thread-private, program-order safe) ----
        const float* Srd = (n==0) ? (S0b + (size_t)512*D) : Sw;
        const float* pR = Srd + (size_t)jg*D + v0;
        u64 sA1 = *(const u64*)pR;
        u64 sA2 = *(const u64*)(pR + 512*D);
        u64 sB1 = *(const u64*)(pR + 32*D);
        u64 sB2 = *(const u64*)(pR + 32*D + 512*D);

        // ---- pred reduce (tid<256); prefetch V/gamma/gates; overlapped norm wait
        u64 p2 = 0ull;
        float2 vv = make_float2(0.f,0.f);
        float ga = 0.f;
        if (tid < 256){
            u64 ps = 0ull;
            #pragma unroll
            for (int g=0;g<16;g++) ps = ADD2(ps, RED[(g*16 + rc)*16 + rpi]);
            p2 = FMA2(c0_2, PM0[rpi], ps);
            vv = *(const float2*)(g_KVQ + ((size_t)b*SEQ + n*CWIN + rc)*1536 + 512 + vt*32 + 2*rpi);
            ga = g_gamma[(b*NCH + n)*CWIN + rc];
        }
        int gi = b*NCH + n;
        float alf0 = g_alpha[gi], thf = g_theta[gi], etf = g_eta[gi];
        if (tid==0 && n>0){
            unsigned target = 16u*(unsigned)n;
            while (atomicAdd(&g_ctr[b], 0u) < target) __nanosleep(32);
            __threadfence();
            float ss = 0.f;
            const float* pp = g_part2 + ((n-1)&1)*BB*16 + b*16;
            #pragma unroll
            for (int i=0;i<16;i++) ss += __ldcg(&pp[i]);
            SBC[0] = fminf(50.0f/(sqrtf(ss)+1e-6f), 1.0f);
        }
        __syncthreads();                                 // sync 3
        float s_prev = (n>0) ? SBC[0] : 1.0f;

        // ---- write pending y(n-1), compute err(n) into ERS2[pi][c] ----
        if (tid < 256){
            if (n>0){
                float ya,yb; UNPK(yv_pend, ya, yb);
                *(float2*)&g_Y[((size_t)b*SEQ + (n-1)*CWIN + rc)*D + vt*32 + 2*rpi]
                    = make_float2(s_prev*ya, s_prev*yb);
            }
            float pa,pb; UNPK(p2, pa, pb);
            float ea = ga*(pa*s_prev - vv.x);
            float eb = ga*(pb*s_prev - vv.y);
            ERS2[rpi*16 + rc] = PK2(ea, eb);
        }
        __syncthreads();                                 // sync 4

        float alf = alf0*s_prev;

        // ---- row-0 moment update (threads tid<16) ----
        if (tid < 16){
            u64 esum = 0ull;
            #pragma unroll
            for (int c=0;c<16;c++) esum = ADD2(esum, ERS2[tid*16 + c]);
            float ge = etf*f0;
            u64 g   = MUL2(PK2(ge,ge), esum);
            u64 thv = PK2(thf,thf), alv = PK2(alf,alf);
            u64 s1n = FMA2(thv, Ms1, MUL2(PK2(-512.f,-512.f), g));
            u64 thg = MUL2(thv, g);
            u64 s2n = ADD2( FMA2(MUL2(thv,thv), Ms2, MUL2(PK2(-2.f,-2.f), MUL2(thg, Ms1))),
                            MUL2(PK2(512.f,512.f), MUL2(g,g)) );
            u64 msp = FMA2(thv, Mms, MUL2(MUL2(PK2(-1.f,-1.f), g), Mm1));
            u64 m1n = FMA2(alv, Mm1, s1n);
            u64 m2n = ADD2( FMA2(MUL2(alv,alv), Mm2, MUL2(MUL2(PK2(2.f,2.f), alv), msp)), s2n );
            u64 msn = ADD2(MUL2(alv, msp), s2n);
            Mm1=m1n; Ms1=s1n; Mm2=m2n; Ms2=s2n; Mms=msn;
            YM0[tid] = m1n;
            SQM[tid] = m2n;
        }

        // ---- phase B1: grad + M-register update + S stream (depth-2) + sumsq
        u64 sq2 = 0ull;
        {
            u64 e2[16];
            #pragma unroll
            for (int c=0;c<16;c++) e2[c] = ERS2[pi*16 + c];

            u64 al = PK2(alf,alf), th = PK2(thf,thf);
            u64 nf1 = PK2(-etf*f1, -etf*f1);
            u64 nf2 = PK2(-etf*f2, -etf*f2);

            const float* pF = pR + 64*D;                // t+2 read cursor
            float*       pW = Sw + (size_t)jg*D + v0;
            #pragma unroll
            for (int t=0;t<16;t++){
                u64 nn1=0ull, nn2=0ull;
                if (t<14){
                    nn1 = *(const u64*)pF;
                    nn2 = *(const u64*)(pF + 512*D);
                    pF += 32*D;
                }
                const ulonglong2* kp = (const ulonglong2*)&KS[(jg + 32*t)*18];
                u64 g1 = 0ull, g2 = 0ull;
                #pragma unroll
                for (int cc=0;cc<8;cc++){
                    ulonglong2 kk = kp[cc];
                    u64 k2a = MUL2(kk.x, kk.x);
                    u64 k2b = MUL2(kk.y, kk.y);
                    g1 = FMA2(kk.x, e2[2*cc],   g1);
                    g2 = FMA2(k2a,  e2[2*cc],   g2);
                    g1 = FMA2(kk.y, e2[2*cc+1], g1);
                    g2 = FMA2(k2b,  e2[2*cc+1], g2);
                }
                u64 sn1 = FMA2(nf1, g1, MUL2(th, sA1));
                u64 sn2 = FMA2(nf2, g2, MUL2(th, sA2));
                u64 mn1 = FMA2(al, rM1[t], sn1);
                u64 mn2 = FMA2(al, rM2[t], sn2);
                *(u64*)(pW)         = sn1;
                *(u64*)(pW + 512*D) = sn2;
                rM1[t] = mn1; rM2[t] = mn2;
                sq2 = FMA2(mn1,mn1,sq2); sq2 = FMA2(mn2,mn2,sq2);
                sA1 = sB1; sA2 = sB2; sB1 = nn1; sB2 = nn2;
                pW += 32*D;
            }
        }
        float sa,sb; UNPK(sq2, sa, sb);
        float sq = wred(sa + sb);
        if (lane==0) WRS[w] = sq;
        __syncthreads();                                 // sync 4b

        // ---- EARLY norm publish ----
        if (tid==0){
            float tot = 0.f;
            #pragma unroll
            for (int i=0;i<16;i++) tot += WRS[i];
            #pragma unroll
            for (int i=0;i<16;i++){
                float qa,qb; UNPK(SQM[i], qa, qb);
                tot += qa + qb;
            }
            g_part2[(n&1)*BB*16 + b*16 + vt] = tot;
            __threadfence();
            atomicAdd(&g_ctr[b], 1u);
        }

        // ---- phase B2: y-read from updated M registers ----
        {
            u64 yacc[16];
            #pragma unroll
            for (int c=0;c<16;c++) yacc[c]=0ull;
            #pragma unroll
            for (int t=0;t<16;t++){
                u64 u1 = MUL2(c1_2, rM1[t]);
                u64 u2 = MUL2(c2_2, rM2[t]);
                const ulonglong2* qp = (const ulonglong2*)&QS[(jg + 32*t)*18];
                #pragma unroll
                for (int cc=0;cc<8;cc++){
                    ulonglong2 qq = qp[cc];
                    yacc[2*cc]   = FMA2(qq.x, FMA2(qq.x, u2, u1), yacc[2*cc]);
                    yacc[2*cc+1] = FMA2(qq.y, FMA2(qq.y, u2, u1), yacc[2*cc+1]);
                }
            }
            #pragma unroll
            for (int c=0;c<16;c++){
                yacc[c] = ADD2(yacc[c], __shfl_down_sync(0xffffffffu, yacc[c], 16));
                if (lane < 16) RED[(w*16 + c)*16 + lane] = yacc[c];
            }
        }
        __syncthreads();                                 // sync 5

        if (tid < 256){
            u64 ys = 0ull;
            #pragma unroll
            for (int g=0;g<16;g++) ys = ADD2(ys, RED[(g*16 + rc)*16 + rpi]);
            yv_pend = FMA2(c0_2, YM0[rpi], ys);
        }
    }

    // ---- tail: y for chunk 127 ----
    __syncthreads();
    if (tid==0){
        unsigned target = 16u*NCH;
        while (atomicAdd(&g_ctr[b], 0u) < target) __nanosleep(32);
        __threadfence();
        float ss = 0.f;
        const float* pp = g_part2 + ((NCH-1)&1)*BB*16 + b*16;
        #pragma unroll
        for (int i=0;i<16;i++) ss += __ldcg(&pp[i]);
        SBC[0] = fminf(50.0f/(sqrtf(ss)+1e-6f), 1.0f);
    }
    __syncthreads();
    if (tid < 256){
        float s = SBC[0];
        float ya,yb; UNPK(yv_pend, ya, yb);
        *(float2*)&g_Y[((size_t)b*SEQ + (NCH-1)*CWIN + rc)*D + vt*32 + 2*rpi]
            = make_float2(s*ya, s*yb);
    }
}

// ---------------- launch ----------------
extern "C" void kernel_launch(void* const* d_in, const int* in_sizes, int n_in,
                              void* d_out, int out_size)
{
    const float* x     = (const float*)d_in[0];
    const float* M0    = (const float*)d_in[1];
    const float* S0    = (const float*)d_in[2];
    const float* Wk    = (const float*)d_in[3];
    const float* Wv    = (const float*)d_in[4];
    const float* Wq    = (const float*)d_in[5];
    const float* Wqk   = (const float*)d_in[6];
    const float* Wout  = (const float*)d_in[7];
    const float* coeffs= (const float*)d_in[8];
    const float* cgWq  = (const float*)d_in[9];
    const float* cgWk  = (const float*)d_in[10];
    const float* temp  = (const float*)d_in[11];
    const float* aw    = (const float*)d_in[12];
    const float* ab    = (const float*)d_in[13];
    const float* tw    = (const float*)d_in[14];
    const float* tb    = (const float*)d_in[15];
    const float* ew    = (const float*)d_in[16];
    const float* eb    = (const float*)d_in[17];
    float* out = (float*)d_out;

    float *pKVQ,*pW3,*pY,*pXl,*pQG,*pT;
    cudaGetSymbolAddress((void**)&pKVQ, g_KVQ);
    cudaGetSymbolAddress((void**)&pW3,  g_W3);
    cudaGetSymbolAddress((void**)&pY,   g_Y);
    cudaGetSymbolAddress((void**)&pXl,  g_Xlast);
    cudaGetSymbolAddress((void**)&pQG,  g_QG);
    cudaGetSymbolAddress((void**)&pT,   g_T);

    cudaFuncSetAttribute(chunk_loop_kernel,
                         cudaFuncAttributeMaxDynamicSharedMemorySize, SM_TOT);

    zero_ctrs<<<1,32>>>();

    // W3 = [Wk; Wv; Wqk@Wq], then ONE merged projection GEMM
    cudaMemcpyAsync(pW3,          Wk, sizeof(float)*512*512, cudaMemcpyDeviceToDevice);
    cudaMemcpyAsync(pW3+512*512,  Wv, sizeof(float)*512*512, cudaMemcpyDeviceToDevice);
    gemm_kernel<false><<<dim3(4,4),  256>>>(Wqk, Wq, pW3+1024*512, 512, 512, 512);
    gemm_kernel<true ><<<dim3(12,128),256>>>(x, pW3, pKVQ, BB*SEQ, 1536, 512);

    // gates
    gather_xlast<<<2048,256>>>(x);
    gemm_kernel<true ><<<dim3(4,8),256>>>(pXl, cgWq, pQG, BB*NCH, 512, 512);
    gemm_kernel<false><<<dim3(4,8),256>>>(pQG, cgWk, pT,  BB*NCH, 512, 512);
    gates_kernel<<<BB*NCH,128>>>(x, temp, aw, ab, tw, tb, ew, eb);

    // entire 128-chunk recurrence in ONE persistent kernel (M in registers)
    chunk_loop_kernel<<<dim3(16,8),512,SM_TOT>>>(coeffs, M0, S0);

    // out = Y @ Wout^T
    gemm_kernel<true><<<dim3(4,128),256>>>(pY, Wout, out, BB*SEQ, 512, 512);
}

// round 17
// speedup vs baseline: 1.2187x; 1.1626x over previous
#include <cuda_runtime.h>
#include <math.h>

#define BB   8
#define SEQ  2048
#define D    512
#define CWIN 16
#define NCH  128
#define DP   1536

typedef unsigned long long u64;

// ---------------- persistent device scratch ----------------
__device__ float g_KVQ[(size_t)BB*SEQ*1536];   // per token: [k 512 | v 512 | q 512]
__device__ float g_W3[1536*512];               // [Wk; Wv; Wqk@Wq]
__device__ float g_Y[BB*SEQ*D];
__device__ float g_S2[(size_t)BB*1024*D];      // S rows 1,2 only
__device__ float g_Xlast[BB*NCH*D];
__device__ float g_QG[BB*NCH*D];
__device__ float g_T[BB*NCH*D];
__device__ float g_gamma[BB*NCH*CWIN];
__device__ float g_alpha[BB*NCH];
__device__ float g_theta[BB*NCH];
__device__ float g_eta[BB*NCH];
__device__ float g_part2[2*BB*16];
__device__ unsigned int g_ctr[BB];

// ---------------- f32x2 packed helpers (sm_100+) ----------------
__device__ __forceinline__ u64 PK2(float lo, float hi){
    u64 r; asm("mov.b64 %0, {%1,%2};" : "=l"(r) : "f"(lo), "f"(hi)); return r;
}
__device__ __forceinline__ void UNPK(u64 v, float& a, float& b){
    asm("mov.b64 {%0,%1}, %2;" : "=f"(a), "=f"(b) : "l"(v));
}
__device__ __forceinline__ u64 FMA2(u64 a, u64 b, u64 c){
    u64 d; asm("fma.rn.f32x2 %0,%1,%2,%3;" : "=l"(d) : "l"(a), "l"(b), "l"(c)); return d;
}
__device__ __forceinline__ u64 MUL2(u64 a, u64 b){
    u64 d; asm("mul.rn.f32x2 %0,%1,%2;" : "=l"(d) : "l"(a), "l"(b)); return d;
}
__device__ __forceinline__ u64 ADD2(u64 a, u64 b){
    u64 d; asm("add.rn.f32x2 %0,%1,%2;" : "=l"(d) : "l"(a), "l"(b)); return d;
}
__device__ __forceinline__ unsigned CVT_TF32(float x){
    unsigned r; asm("cvt.rna.tf32.f32 %0, %1;" : "=r"(r) : "f"(x)); return r;
}

__device__ __forceinline__ float wred(float x){
    #pragma unroll
    for (int o=16;o;o>>=1) x += __shfl_down_sync(0xffffffffu, x, o);
    return x;
}

// ---------------- fp32 GEMM (NN path only): double-buffered, 2 CTAs/SM ----
template<bool NT>
__global__ void __launch_bounds__(256,2) gemm_kernel(const float* __restrict__ A,
                                                     const float* __restrict__ Bm,
                                                     float* __restrict__ Cm,
                                                     int M, int N, int K)
{
    __shared__ float As[2][16][132];
    __shared__ float Bs[2][16][132];
    int tid = threadIdx.x;
    int m0 = blockIdx.y * 128, n0 = blockIdx.x * 128;
    int ty = tid >> 4, tx = tid & 15;

    int row0 = tid >> 2,          k40 = (tid & 3)*4;
    int row1 = (tid+256) >> 2,    k41 = k40;
    int kr0  = tid >> 5,          n40 = (tid & 31)*4;
    int kr1  = (tid+256) >> 5,    n41 = n40;

    u64 acc2[8][4];
    #pragma unroll
    for (int i=0;i<8;i++)
        #pragma unroll
        for (int j=0;j<4;j++) acc2[i][j]=0ull;

    float4 ra0, ra1, rb0, rb1;

    ra0 = *(const float4*)(A + (size_t)(m0+row0)*K + k40);
    ra1 = *(const float4*)(A + (size_t)(m0+row1)*K + k41);
    if (NT){
        rb0 = *(const float4*)(Bm + (size_t)(n0+row0)*K + k40);
        rb1 = *(const float4*)(Bm + (size_t)(n0+row1)*K + k41);
    } else {
        rb0 = *(const float4*)(Bm + (size_t)(kr0)*N + n0 + n40);
        rb1 = *(const float4*)(Bm + (size_t)(kr1)*N + n0 + n41);
    }
    As[0][k40+0][row0]=ra0.x; As[0][k40+1][row0]=ra0.y; As[0][k40+2][row0]=ra0.z; As[0][k40+3][row0]=ra0.w;
    As[0][k41+0][row1]=ra1.x; As[0][k41+1][row1]=ra1.y; As[0][k41+2][row1]=ra1.z; As[0][k41+3][row1]=ra1.w;
    if (NT){
        Bs[0][k40+0][row0]=rb0.x; Bs[0][k40+1][row0]=rb0.y; Bs[0][k40+2][row0]=rb0.z; Bs[0][k40+3][row0]=rb0.w;
        Bs[0][k41+0][row1]=rb1.x; Bs[0][k41+1][row1]=rb1.y; Bs[0][k41+2][row1]=rb1.z; Bs[0][k41+3][row1]=rb1.w;
    } else {
        *(float4*)&Bs[0][kr0][n40] = rb0;
        *(float4*)&Bs[0][kr1][n41] = rb1;
    }
    __syncthreads();

    int nk = K >> 4;
    for (int t=0;t<nk;t++){
        if (t+1 < nk){
            int k0 = (t+1)*16;
            ra0 = *(const float4*)(A + (size_t)(m0+row0)*K + k0 + k40);
            ra1 = *(const float4*)(A + (size_t)(m0+row1)*K + k0 + k41);
            if (NT){
                rb0 = *(const float4*)(Bm + (size_t)(n0+row0)*K + k0 + k40);
                rb1 = *(const float4*)(Bm + (size_t)(n0+row1)*K + k0 + k41);
            } else {
                rb0 = *(const float4*)(Bm + (size_t)(k0+kr0)*N + n0 + n40);
                rb1 = *(const float4*)(Bm + (size_t)(k0+kr1)*N + n0 + n41);
            }
        }
        int bf = t & 1;
        #pragma unroll
        for (int kk=0;kk<16;kk++){
            float a[8];
            *(float4*)(a)   = *(const float4*)&As[bf][kk][ty*8];
            *(float4*)(a+4) = *(const float4*)&As[bf][kk][ty*8+4];
            u64 b2[4];
            *(ulonglong2*)&b2[0] = *(const ulonglong2*)&Bs[bf][kk][tx*8];
            *(ulonglong2*)&b2[2] = *(const ulonglong2*)&Bs[bf][kk][tx*8+4];
            #pragma unroll
            for (int i=0;i<8;i++){
                u64 ai = PK2(a[i], a[i]);
                #pragma unroll
                for (int jp=0;jp<4;jp++) acc2[i][jp] = FMA2(ai, b2[jp], acc2[i][jp]);
            }
        }
        if (t+1 < nk){
            int nb = (t+1) & 1;
            As[nb][k40+0][row0]=ra0.x; As[nb][k40+1][row0]=ra0.y; As[nb][k40+2][row0]=ra0.z; As[nb][k40+3][row0]=ra0.w;
            As[nb][k41+0][row1]=ra1.x; As[nb][k41+1][row1]=ra1.y; As[nb][k41+2][row1]=ra1.z; As[nb][k41+3][row1]=ra1.w;
            if (NT){
                Bs[nb][k40+0][row0]=rb0.x; Bs[nb][k40+1][row0]=rb0.y; Bs[nb][k40+2][row0]=rb0.z; Bs[nb][k40+3][row0]=rb0.w;
                Bs[nb][k41+0][row1]=rb1.x; Bs[nb][k41+1][row1]=rb1.y; Bs[nb][k41+2][row1]=rb1.z; Bs[nb][k41+3][row1]=rb1.w;
            } else {
                *(float4*)&Bs[nb][kr0][n40] = rb0;
                *(float4*)&Bs[nb][kr1][n41] = rb1;
            }
            __syncthreads();
        }
    }
    #pragma unroll
    for (int i=0;i<8;i++){
        float o[8];
        #pragma unroll
        for (int jp=0;jp<4;jp++) UNPK(acc2[i][jp], o[2*jp], o[2*jp+1]);
        size_t r = (size_t)(m0 + ty*8 + i)*N + n0 + tx*8;
        *(float4*)(Cm + r)     = make_float4(o[0],o[1],o[2],o[3]);
        *(float4*)(Cm + r + 4) = make_float4(o[4],o[5],o[6],o[7]);
    }
}

// ---------------- TF32 tensor-core NT GEMM: C[M,N] = A[M,K] @ B[N,K]^T ----
// 256 thr / 8 warps; block tile 128x128, warp tile 32x64, mma m16n8k8.
// smem rows hold k interleaved as pairs (k, k+4) so each fragment is one
// conflict-free LDS.64. Row pad = 24 floats (conflict-free for both phases).
#define TGEMM_SMEM 49152   // 2 buf x (A 128*24 + B 128*24) * 4B

__global__ void __launch_bounds__(256,2) tf32_gemm_nt(const float* __restrict__ A,
                                                      const float* __restrict__ Bm,
                                                      float* __restrict__ Cm,
                                                      int M, int N, int K)
{
    extern __shared__ unsigned tsm[];
    unsigned* Ab = tsm;                 // [2][128][24]
    unsigned* Bb = tsm + 2*128*24;      // [2][128][24]

    const int tid = threadIdx.x;
    const int lane = tid & 31, w = tid >> 5;
    const int wr = w >> 1, wc = w & 1;          // warp grid 4x2
    const int m0 = blockIdx.y * 128, n0 = blockIdx.x * 128;

    const int rowA = tid >> 2;                  // 0..63
    const int k4   = (tid & 3) * 4;             // 0,4,8,12
    // staging column map for the 4 loaded k values
    int cols[4];
    #pragma unroll
    for (int j=0;j<4;j++){
        int ks = k4 + j, g = ks >> 3, kk = ks & 7;
        cols[j] = g*8 + (kk & 3)*2 + (kk >> 2);
    }

    float acc[2][8][4];
    #pragma unroll
    for (int mt=0;mt<2;mt++)
        #pragma unroll
        for (int nt=0;nt<8;nt++)
            #pragma unroll
            for (int i=0;i<4;i++) acc[mt][nt][i] = 0.f;

    float4 ra0, ra1, rb0, rb1;
    // prologue: tile 0
    ra0 = *(const float4*)(A  + (size_t)(m0+rowA)   *K + k4);
    ra1 = *(const float4*)(A  + (size_t)(m0+rowA+64)*K + k4);
    rb0 = *(const float4*)(Bm + (size_t)(n0+rowA)   *K + k4);
    rb1 = *(const float4*)(Bm + (size_t)(n0+rowA+64)*K + k4);
    {
        float a0v[4]={ra0.x,ra0.y,ra0.z,ra0.w}, a1v[4]={ra1.x,ra1.y,ra1.z,ra1.w};
        float b0v[4]={rb0.x,rb0.y,rb0.z,rb0.w}, b1v[4]={rb1.x,rb1.y,rb1.z,rb1.w};
        #pragma unroll
        for (int j=0;j<4;j++){
            Ab[rowA*24      + cols[j]] = CVT_TF32(a0v[j]);
            Ab[(rowA+64)*24 + cols[j]] = CVT_TF32(a1v[j]);
            Bb[rowA*24      + cols[j]] = CVT_TF32(b0v[j]);
            Bb[(rowA+64)*24 + cols[j]] = CVT_TF32(b1v[j]);
        }
    }
    __syncthreads();

    const int nk = K >> 4;
    for (int t=0;t<nk;t++){
        if (t+1 < nk){
            int k0 = (t+1)*16;
            ra0 = *(const float4*)(A  + (size_t)(m0+rowA)   *K + k0 + k4);
            ra1 = *(const float4*)(A  + (size_t)(m0+rowA+64)*K + k0 + k4);
            rb0 = *(const float4*)(Bm + (size_t)(n0+rowA)   *K + k0 + k4);
            rb1 = *(const float4*)(Bm + (size_t)(n0+rowA+64)*K + k0 + k4);
        }
        const unsigned* Abuf = Ab + (t&1)*128*24;
        const unsigned* Bbuf = Bb + (t&1)*128*24;
        #pragma unroll
        for (int s=0;s<2;s++){
            unsigned af[2][4];
            #pragma unroll
            for (int mt=0;mt<2;mt++){
                int mrow = wr*32 + mt*16 + (lane>>2);
                u64 lo = *(const u64*)&Abuf[mrow*24     + s*8 + (lane&3)*2];
                u64 hi = *(const u64*)&Abuf[(mrow+8)*24 + s*8 + (lane&3)*2];
                af[mt][0] = (unsigned)lo; af[mt][2] = (unsigned)(lo>>32);
                af[mt][1] = (unsigned)hi; af[mt][3] = (unsigned)(hi>>32);
            }
            unsigned bf_[8][2];
            #pragma unroll
            for (int nt=0;nt<8;nt++){
                int nrow = wc*64 + nt*8 + (lane>>2);
                u64 bv = *(const u64*)&Bbuf[nrow*24 + s*8 + (lane&3)*2];
                bf_[nt][0] = (unsigned)bv; bf_[nt][1] = (unsigned)(bv>>32);
            }
            #pragma unroll
            for (int mt=0;mt<2;mt++)
                #pragma unroll
                for (int nt=0;nt<8;nt++){
                    asm volatile(
                        "mma.sync.aligned.m16n8k8.row.col.f32.tf32.tf32.f32 "
                        "{%0,%1,%2,%3},{%4,%5,%6,%7},{%8,%9},{%0,%1,%2,%3};"
                        : "+f"(acc[mt][nt][0]), "+f"(acc[mt][nt][1]),
                          "+f"(acc[mt][nt][2]), "+f"(acc[mt][nt][3])
                        : "r"(af[mt][0]), "r"(af[mt][1]), "r"(af[mt][2]), "r"(af[mt][3]),
                          "r"(bf_[nt][0]), "r"(bf_[nt][1]));
                }
        }
        if (t+1 < nk){
            unsigned* An = Ab + ((t+1)&1)*128*24;
            unsigned* Bn = Bb + ((t+1)&1)*128*24;
            float a0v[4]={ra0.x,ra0.y,ra0.z,ra0.w}, a1v[4]={ra1.x,ra1.y,ra1.z,ra1.w};
            float b0v[4]={rb0.x,rb0.y,rb0.z,rb0.w}, b1v[4]={rb1.x,rb1.y,rb1.z,rb1.w};
            #pragma unroll
            for (int j=0;j<4;j++){
                An[rowA*24      + cols[j]] = CVT_TF32(a0v[j]);
                An[(rowA+64)*24 + cols[j]] = CVT_TF32(a1v[j]);
                Bn[rowA*24      + cols[j]] = CVT_TF32(b0v[j]);
                Bn[(rowA+64)*24 + cols[j]] = CVT_TF32(b1v[j]);
            }
            __syncthreads();
        }
    }

    #pragma unroll
    for (int mt=0;mt<2;mt++)
        #pragma unroll
        for (int nt=0;nt<8;nt++){
            int row = m0 + wr*32 + mt*16 + (lane>>2);
            int col = n0 + wc*64 + nt*8 + (lane&3)*2;
            *(float2*)(Cm + (size_t)row*N + col)     = make_float2(acc[mt][nt][0], acc[mt][nt][1]);
            *(float2*)(Cm + (size_t)(row+8)*N + col) = make_float2(acc[mt][nt][2], acc[mt][nt][3]);
        }
}

// ---------------- gather last token of each chunk ----------------
__global__ void gather_xlast(const float* __restrict__ x){
    int i = blockIdx.x*256 + threadIdx.x;
    if (i < BB*NCH*D){
        int e = i & 511; int r = i >> 9; int b = r >> 7; int n = r & 127;
        g_Xlast[i] = x[((size_t)b*SEQ + n*CWIN + (CWIN-1))*D + e];
    }
}

__global__ void zero_ctrs(){
    int i = threadIdx.x;
    if (i < BB) g_ctr[i] = 0u;
}

// ---------------- gates ----------------
__global__ void __launch_bounds__(128) gates_kernel(const float* __restrict__ x,
    const float* __restrict__ temp,
    const float* __restrict__ aw, const float* __restrict__ ab,
    const float* __restrict__ tw, const float* __restrict__ tb,
    const float* __restrict__ ew, const float* __restrict__ eb)
{
    int r = blockIdx.x; int b = r >> 7; int n = r & 127;
    int tid = threadIdx.x, w = tid >> 5, lane = tid & 31;
    __shared__ float ts[512];
    __shared__ float accA[16], accT[16], accE[16];
    for (int i=tid;i<512;i+=128) ts[i] = g_T[(size_t)r*512 + i];
    __syncthreads();
    float invt = 1.0f/(22.627416997969522f * fmaxf(temp[0], 0.1f));
    for (int c=w;c<16;c+=4){
        const float* xr = x + ((size_t)b*SEQ + n*CWIN + c)*D;
        float gs=0.f, as=0.f, tws=0.f, es=0.f;
        for (int e=lane;e<512;e+=32){
            float xv = xr[e];
            gs  = fmaf(xv, ts[e], gs);
            as  = fmaf(xv, aw[e], as);
            tws = fmaf(xv, tw[e], tws);
            es  = fmaf(xv, ew[e], es);
        }
        gs = wred(gs); as = wred(as); tws = wred(tws); es = wred(es);
        if (lane==0){
            g_gamma[(size_t)r*CWIN + c] = 1.f/(1.f + expf(-gs*invt));
            accA[c]=as; accT[c]=tws; accE[c]=es;
        }
    }
    __syncthreads();
    if (tid==0){
        float sa=0.f, st=0.f, se=0.f;
        for (int c=0;c<16;c++){ sa+=accA[c]; st+=accT[c]; se+=accE[c]; }
        sa = sa*(1.f/16.f) + ab[0];
        st = st*(1.f/16.f) + tb[0];
        se = se*(1.f/16.f) + eb[0];
        g_alpha[r] = 1.f/(1.f+expf(-sa));
        g_theta[r] = 1.f/(1.f+expf(-st));
        g_eta[r]   = 1.f/(1.f+expf(-se));
    }
}

// ---------------- persistent chunk-recurrence kernel (R13 exact) ----------
#define SM_KS    0           // u64[512*18]  splat (k,k)     73728 B
#define SM_QS    73728       // u64[512*18]  splat (q,q)     73728 B
#define SM_RED   147456      // u64[16*16*16]                32768 B
#define SM_ERS2  180224      // u64[16 pi][16 c]              2048 B
#define SM_WRS   182272      // float[16]
#define SM_SBC   182336      // float
#define SM_PM0   182400      // u64[16]
#define SM_YM0   182528      // u64[16]
#define SM_SQM   182656      // u64[16]
#define SM_TOT   182784

__global__ void __launch_bounds__(512,1) chunk_loop_kernel(const float* __restrict__ coeffs,
                                                           const float* __restrict__ M0g,
                                                           const float* __restrict__ S0g)
{
    extern __shared__ char smraw[];
    u64*   KS   = (u64*)(smraw + SM_KS);
    u64*   QS   = (u64*)(smraw + SM_QS);
    u64*   RED  = (u64*)(smraw + SM_RED);
    u64*   ERS2 = (u64*)(smraw + SM_ERS2);
    float* WRS  = (float*)(smraw + SM_WRS);
    float* SBC  = (float*)(smraw + SM_SBC);
    u64*   PM0  = (u64*)(smraw + SM_PM0);
    u64*   YM0  = (u64*)(smraw + SM_YM0);
    u64*   SQM  = (u64*)(smraw + SM_SQM);

    const int b = blockIdx.y, vt = blockIdx.x;
    const int tid = threadIdx.x;
    const int pi = tid & 15, jg = tid >> 4;
    const int w = tid >> 5, lane = tid & 31;
    const int v0 = vt*32 + 2*pi;
    const int rc = tid >> 4, rpi = tid & 15;

    const float c0 = coeffs[0], c1 = coeffs[1], c2 = coeffs[2];
    const u64 c0_2 = PK2(c0,c0), c1_2 = PK2(c1,c1), c2_2 = PK2(c2,c2);
    const float f0 = 0.125f*c0, f1 = 0.125f*c1, f2 = 0.125f*c2;

    const float* M0b = M0g + (size_t)b*DP*D;
    const float* S0b = S0g + (size_t)b*DP*D;
    float* Sw = g_S2 + (size_t)b*1024*D;

    // ---- initial row-0 moments (threads tid<16) ----
    u64 Mm1=0ull, Ms1=0ull, Mm2=0ull, Ms2=0ull, Mms=0ull;
    if (tid < 16){
        const float* pm = M0b + vt*32 + 2*tid;
        const float* ps = S0b + vt*32 + 2*tid;
        #pragma unroll 4
        for (int j=0;j<512;j++){
            u64 m = *(const u64*)(pm + (size_t)j*D);
            u64 s = *(const u64*)(ps + (size_t)j*D);
            Mm1 = ADD2(Mm1, m); Ms1 = ADD2(Ms1, s);
            Mm2 = FMA2(m,m,Mm2); Ms2 = FMA2(s,s,Ms2); Mms = FMA2(m,s,Mms);
        }
    }

    // ---- initial register state: rows 1,2 of M (64 regs) ----
    u64 rM1[16], rM2[16];
    #pragma unroll
    for (int t=0;t<16;t++){
        const float* pm = M0b + (size_t)(512 + jg + 32*t)*D + v0;
        rM1[t] = *(const u64*)pm;
        rM2[t] = *(const u64*)(pm + 512*D);
    }

    u64 yv_pend = 0ull;

    for (int n=0;n<NCH;n++){
        // ---- publish pre-update ΣM0; co-stage k AND q splats (j-major) ----
        if (tid < 16) PM0[tid] = Mm1;
        const float* KQc = g_KVQ + ((size_t)b*SEQ + n*CWIN)*1536;
        #pragma unroll
        for (int i=0;i<16;i++){
            int idx = tid + i*512;
            int j = idx & 511, c = idx >> 9;
            float kv = KQc[(size_t)c*1536 + j];
            float qv = KQc[(size_t)c*1536 + 1024 + j];
            KS[j*18 + c] = PK2(kv,kv);
            QS[j*18 + c] = PK2(qv,qv);
        }
        __syncthreads();                                 // sync 1

        // ---- phase A: pred partials (M from registers) ----
        u64 acc[16];
        #pragma unroll
        for (int c=0;c<16;c++) acc[c]=0ull;
        #pragma unroll
        for (int t=0;t<16;t++){
            u64 t1 = MUL2(c1_2, rM1[t]), t2 = MUL2(c2_2, rM2[t]);
            const ulonglong2* kp = (const ulonglong2*)&KS[(jg + 32*t)*18];
            #pragma unroll
            for (int cc=0;cc<8;cc++){
                ulonglong2 kk = kp[cc];
                acc[2*cc]   = FMA2(kk.x, FMA2(kk.x, t2, t1), acc[2*cc]);
                acc[2*cc+1] = FMA2(kk.y, FMA2(kk.y, t2, t1), acc[2*cc+1]);
            }
        }
        #pragma unroll
        for (int c=0;c<16;c++){
            acc[c] = ADD2(acc[c], __shfl_down_sync(0xffffffffu, acc[c], 16));
            if (lane < 16) RED[(w*16 + c)*16 + lane] = acc[c];
        }
        __syncthreads();                                 // sync 2

        // ---- pred reduce (tid<256); prefetch V/gamma/gates; overlapped norm wait
        u64 p2 = 0ull;
        float2 vv = make_float2(0.f,0.f);
        float ga = 0.f;
        if (tid < 256){
            u64 ps = 0ull;
            #pragma unroll
            for (int g=0;g<16;g++) ps = ADD2(ps, RED[(g*16 + rc)*16 + rpi]);
            p2 = FMA2(c0_2, PM0[rpi], ps);
            vv = *(const float2*)(g_KVQ + ((size_t)b*SEQ + n*CWIN + rc)*1536 + 512 + vt*32 + 2*rpi);
            ga = g_gamma[(b*NCH + n)*CWIN + rc];
        }
        int gi = b*NCH + n;
        float alf0 = g_alpha[gi], thf = g_theta[gi], etf = g_eta[gi];
        if (tid==0 && n>0){
            unsigned target = 16u*(unsigned)n;
            while (atomicAdd(&g_ctr[b], 0u) < target) __nanosleep(32);
            __threadfence();
            float ss = 0.f;
            const float* pp = g_part2 + ((n-1)&1)*BB*16 + b*16;
            #pragma unroll
            for (int i=0;i<16;i++) ss += __ldcg(&pp[i]);
            SBC[0] = fminf(50.0f/(sqrtf(ss)+1e-6f), 1.0f);
        }
        __syncthreads();                                 // sync 3
        float s_prev = (n>0) ? SBC[0] : 1.0f;

        // ---- write pending y(n-1), compute err(n) into ERS2[pi][c] ----
        if (tid < 256){
            if (n>0){
                float ya,yb; UNPK(yv_pend, ya, yb);
                *(float2*)&g_Y[((size_t)b*SEQ + (n-1)*CWIN + rc)*D + vt*32 + 2*rpi]
                    = make_float2(s_prev*ya, s_prev*yb);
            }
            float pa,pb; UNPK(p2, pa, pb);
            float ea = ga*(pa*s_prev - vv.x);
            float eb = ga*(pb*s_prev - vv.y);
            ERS2[rpi*16 + rc] = PK2(ea, eb);
        }
        __syncthreads();                                 // sync 4

        float alf = alf0*s_prev;

        // ---- row-0 moment update (threads tid<16) ----
        if (tid < 16){
            u64 esum = 0ull;
            #pragma unroll
            for (int c=0;c<16;c++) esum = ADD2(esum, ERS2[tid*16 + c]);
            float ge = etf*f0;
            u64 g   = MUL2(PK2(ge,ge), esum);
            u64 thv = PK2(thf,thf), alv = PK2(alf,alf);
            u64 s1n = FMA2(thv, Ms1, MUL2(PK2(-512.f,-512.f), g));
            u64 thg = MUL2(thv, g);
            u64 s2n = ADD2( FMA2(MUL2(thv,thv), Ms2, MUL2(PK2(-2.f,-2.f), MUL2(thg, Ms1))),
                            MUL2(PK2(512.f,512.f), MUL2(g,g)) );
            u64 msp = FMA2(thv, Mms, MUL2(MUL2(PK2(-1.f,-1.f), g), Mm1));
            u64 m1n = FMA2(alv, Mm1, s1n);
            u64 m2n = ADD2( FMA2(MUL2(alv,alv), Mm2, MUL2(MUL2(PK2(2.f,2.f), alv), msp)), s2n );
            u64 msn = ADD2(MUL2(alv, msp), s2n);
            Mm1=m1n; Ms1=s1n; Mm2=m2n; Ms2=s2n; Mms=msn;
            YM0[tid] = m1n;
            SQM[tid] = m2n;
        }

        // ---- phase B1: grad + M-register update + S stream + sumsq ----
        u64 sq2 = 0ull;
        {
            u64 e2[16];
            #pragma unroll
            for (int c=0;c<16;c++) e2[c] = ERS2[pi*16 + c];

            u64 al = PK2(alf,alf), th = PK2(thf,thf);
            u64 nf1 = PK2(-etf*f1, -etf*f1);
            u64 nf2 = PK2(-etf*f2, -etf*f2);

            const float* Srd = (n==0) ? (S0b + (size_t)512*D) : Sw;
            const float* pR = Srd + (size_t)jg*D + v0;
            float*       pW = Sw  + (size_t)jg*D + v0;
            u64 so1 = *(const u64*)pR;
            u64 so2 = *(const u64*)(pR + 512*D);
            #pragma unroll
            for (int t=0;t<16;t++){
                const float* pRn = pR + 32*D;
                u64 nso1=0ull, nso2=0ull;
                if (t<15){ nso1 = *(const u64*)pRn; nso2 = *(const u64*)(pRn + 512*D); }
                const ulonglong2* kp = (const ulonglong2*)&KS[(jg + 32*t)*18];
                u64 g1 = 0ull, g2 = 0ull;
                #pragma unroll
                for (int cc=0;cc<8;cc++){
                    ulonglong2 kk = kp[cc];
                    u64 k2a = MUL2(kk.x, kk.x);
                    u64 k2b = MUL2(kk.y, kk.y);
                    g1 = FMA2(kk.x, e2[2*cc],   g1);
                    g2 = FMA2(k2a,  e2[2*cc],   g2);
                    g1 = FMA2(kk.y, e2[2*cc+1], g1);
                    g2 = FMA2(k2b,  e2[2*cc+1], g2);
                }
                u64 sn1 = FMA2(nf1, g1, MUL2(th, so1));
                u64 sn2 = FMA2(nf2, g2, MUL2(th, so2));
                u64 mn1 = FMA2(al, rM1[t], sn1);
                u64 mn2 = FMA2(al, rM2[t], sn2);
                *(u64*)(pW)         = sn1;
                *(u64*)(pW + 512*D) = sn2;
                rM1[t] = mn1; rM2[t] = mn2;
                sq2 = FMA2(mn1,mn1,sq2); sq2 = FMA2(mn2,mn2,sq2);
                so1 = nso1; so2 = nso2; pR = pRn; pW += 32*D;
            }
        }
        float sa,sb; UNPK(sq2, sa, sb);
        float sq = wred(sa + sb);
        if (lane==0) WRS[w] = sq;
        __syncthreads();                                 // sync 4b

        // ---- EARLY norm publish ----
        if (tid==0){
            float tot = 0.f;
            #pragma unroll
            for (int i=0;i<16;i++) tot += WRS[i];
            #pragma unroll
            for (int i=0;i<16;i++){
                float qa,qb; UNPK(SQM[i], qa, qb);
                tot += qa + qb;
            }
            g_part2[(n&1)*BB*16 + b*16 + vt] = tot;
            __threadfence();
            atomicAdd(&g_ctr[b], 1u);
        }

        // ---- phase B2: y-read from updated M registers ----
        {
            u64 yacc[16];
            #pragma unroll
            for (int c=0;c<16;c++) yacc[c]=0ull;
            #pragma unroll
            for (int t=0;t<16;t++){
                u64 u1 = MUL2(c1_2, rM1[t]);
                u64 u2 = MUL2(c2_2, rM2[t]);
                const ulonglong2* qp = (const ulonglong2*)&QS[(jg + 32*t)*18];
                #pragma unroll
                for (int cc=0;cc<8;cc++){
                    ulonglong2 qq = qp[cc];
                    yacc[2*cc]   = FMA2(qq.x, FMA2(qq.x, u2, u1), yacc[2*cc]);
                    yacc[2*cc+1] = FMA2(qq.y, FMA2(qq.y, u2, u1), yacc[2*cc+1]);
                }
            }
            #pragma unroll
            for (int c=0;c<16;c++){
                yacc[c] = ADD2(yacc[c], __shfl_down_sync(0xffffffffu, yacc[c], 16));
                if (lane < 16) RED[(w*16 + c)*16 + lane] = yacc[c];
            }
        }
        __syncthreads();                                 // sync 5

        if (tid < 256){
            u64 ys = 0ull;
            #pragma unroll
            for (int g=0;g<16;g++) ys = ADD2(ys, RED[(g*16 + rc)*16 + rpi]);
            yv_pend = FMA2(c0_2, YM0[rpi], ys);
        }
    }

    // ---- tail: y for chunk 127 ----
    __syncthreads();
    if (tid==0){
        unsigned target = 16u*NCH;
        while (atomicAdd(&g_ctr[b], 0u) < target) __nanosleep(32);
        __threadfence();
        float ss = 0.f;
        const float* pp = g_part2 + ((NCH-1)&1)*BB*16 + b*16;
        #pragma unroll
        for (int i=0;i<16;i++) ss += __ldcg(&pp[i]);
        SBC[0] = fminf(50.0f/(sqrtf(ss)+1e-6f), 1.0f);
    }
    __syncthreads();
    if (tid < 256){
        float s = SBC[0];
        float ya,yb; UNPK(yv_pend, ya, yb);
        *(float2*)&g_Y[((size_t)b*SEQ + (NCH-1)*CWIN + rc)*D + vt*32 + 2*rpi]
            = make_float2(s*ya, s*yb);
    }
}

// ---------------- launch ----------------
extern "C" void kernel_launch(void* const* d_in, const int* in_sizes, int n_in,
                              void* d_out, int out_size)
{
    const float* x     = (const float*)d_in[0];
    const float* M0    = (const float*)d_in[1];
    const float* S0    = (const float*)d_in[2];
    const float* Wk    = (const float*)d_in[3];
    const float* Wv    = (const float*)d_in[4];
    const float* Wq    = (const float*)d_in[5];
    const float* Wqk   = (const float*)d_in[6];
    const float* Wout  = (const float*)d_in[7];
    const float* coeffs= (const float*)d_in[8];
    const float* cgWq  = (const float*)d_in[9];
    const float* cgWk  = (const float*)d_in[10];
    const float* temp  = (const float*)d_in[11];
    const float* aw    = (const float*)d_in[12];
    const float* ab    = (const float*)d_in[13];
    const float* tw    = (const float*)d_in[14];
    const float* tb    = (const float*)d_in[15];
    const float* ew    = (const float*)d_in[16];
    const float* eb    = (const float*)d_in[17];
    float* out = (float*)d_out;

    float *pKVQ,*pW3,*pY,*pXl,*pQG,*pT;
    cudaGetSymbolAddress((void**)&pKVQ, g_KVQ);
    cudaGetSymbolAddress((void**)&pW3,  g_W3);
    cudaGetSymbolAddress((void**)&pY,   g_Y);
    cudaGetSymbolAddress((void**)&pXl,  g_Xlast);
    cudaGetSymbolAddress((void**)&pQG,  g_QG);
    cudaGetSymbolAddress((void**)&pT,   g_T);

    cudaFuncSetAttribute(chunk_loop_kernel,
                         cudaFuncAttributeMaxDynamicSharedMemorySize, SM_TOT);
    cudaFuncSetAttribute(tf32_gemm_nt,
                         cudaFuncAttributeMaxDynamicSharedMemorySize, TGEMM_SMEM);

    zero_ctrs<<<1,32>>>();

    // W3 = [Wk; Wv; Wqk@Wq], then ONE merged projection GEMM (tf32 tensor cores)
    cudaMemcpyAsync(pW3,          Wk, sizeof(float)*512*512, cudaMemcpyDeviceToDevice);
    cudaMemcpyAsync(pW3+512*512,  Wv, sizeof(float)*512*512, cudaMemcpyDeviceToDevice);
    gemm_kernel<false><<<dim3(4,4),  256>>>(Wqk, Wq, pW3+1024*512, 512, 512, 512);
    tf32_gemm_nt<<<dim3(12,128),256,TGEMM_SMEM>>>(x, pW3, pKVQ, BB*SEQ, 1536, 512);

    // gates
    gather_xlast<<<2048,256>>>(x);
    tf32_gemm_nt<<<dim3(4,8),256,TGEMM_SMEM>>>(pXl, cgWq, pQG, BB*NCH, 512, 512);
    gemm_kernel<false><<<dim3(4,8),256>>>(pQG, cgWk, pT,  BB*NCH, 512, 512);
    gates_kernel<<<BB*NCH,128>>>(x, temp, aw, ab, tw, tb, ew, eb);

    // entire 128-chunk recurrence in ONE persistent kernel (M in registers)
    chunk_loop_kernel<<<dim3(16,8),512,SM_TOT>>>(coeffs, M0, S0);

    // out = Y @ Wout^T (tf32 tensor cores)
    tf32_gemm_nt<<<dim3(4,128),256,TGEMM_SMEM>>>(pY, Wout, out, BB*SEQ, 512, 512);
}